// round 7
// baseline (speedup 1.0000x reference)
#include <cuda_runtime.h>

#define NND 100000
#define NE  1600000
#define F0  48
#define H1  32
#define H2  16

// ---------------- scratch (static device globals; allocation is forbidden) ----------------
__device__ int g_is64;
__device__ int g_src[NE];
__device__ int g_dst[NE];
__device__ int g_cnt[NND];
__device__ __align__(16) float g_Y1[NND * H1];   // x @ W1l  (aggregated over edges)
__device__ __align__(16) float g_S1[NND * H1];   // x @ W1r + b1 (self term)
__device__ __align__(16) float g_A1[NND * H1];   // scatter accumulator, layer 1
__device__ __align__(16) float g_Y2[NND * H2];
__device__ __align__(16) float g_S2[NND * H2];
__device__ __align__(16) float g_A2[NND * H2];

// 128-bit vector reduction (sm_90+): 1 instruction adds 4 floats, no return.
__device__ __forceinline__ void red_add_v4(float* p, float4 v) {
    asm volatile("red.global.add.v4.f32 [%0], {%1,%2,%3,%4};"
                 :: "l"(p), "f"(v.x), "f"(v.y), "f"(v.z), "f"(v.w)
                 : "memory");
}

// ---------------- dtype detection: int64 edge_index (LE) has zero odd 32-bit words ----------
__global__ void k_detect(const unsigned int* __restrict__ p32) {
    __shared__ int anynz;
    if (threadIdx.x == 0) anynz = 0;
    __syncthreads();
    if (p32[2 * threadIdx.x + 1] != 0) anynz = 1;   // benign race, same value
    __syncthreads();
    if (threadIdx.x == 0) g_is64 = (anynz == 0);
}

// ---------------- convert edge index to int32 + zero accumulators ----------------
__global__ void k_convert_zero(const void* __restrict__ ei) {
    const int t0 = blockIdx.x * blockDim.x + threadIdx.x;
    const int stride = gridDim.x * blockDim.x;
    const int is64 = g_is64;
    if (is64) {
        const long long* p = (const long long*)ei;
        for (int e = t0; e < NE; e += stride) {
            g_src[e] = (int)p[e];
            g_dst[e] = (int)p[NE + e];
        }
    } else {
        const int* p = (const int*)ei;
        for (int e = t0; e < NE; e += stride) {
            g_src[e] = p[e];
            g_dst[e] = p[NE + e];
        }
    }
    for (int i = t0; i < NND * H1; i += stride) g_A1[i] = 0.f;
    for (int i = t0; i < NND * H2; i += stride) g_A2[i] = 0.f;
    for (int i = t0; i < NND;      i += stride) g_cnt[i] = 0;
}

// ---------------- layer 1 transforms: Y1 = x@W1l, S1 = x@W1r + b1 ----------------
// 256 threads = 8 nodes x 32 output cols. Weights + x rows staged in smem.
__global__ void k_transform1(const float* __restrict__ x,
                             const float* __restrict__ Wl,
                             const float* __restrict__ Wr,
                             const float* __restrict__ b) {
    __shared__ float sWl[F0 * H1];
    __shared__ float sWr[F0 * H1];
    __shared__ float sB[H1];
    __shared__ float sX[8 * F0];
    const int tid = threadIdx.x;
    for (int i = tid; i < F0 * H1; i += 256) { sWl[i] = Wl[i]; sWr[i] = Wr[i]; }
    if (tid < H1) sB[tid] = b[tid];
    const int vbase = blockIdx.x * 8;                    // 100000 % 8 == 0
    for (int i = tid; i < 8 * F0; i += 256) sX[i] = x[vbase * F0 + i];
    __syncthreads();

    const int vloc = tid >> 5;      // warp id == local node (broadcast smem reads)
    const int j    = tid & 31;      // output column (conflict-free weight reads)
    const float* xr = &sX[vloc * F0];
    float al = 0.f, ar = 0.f;
#pragma unroll
    for (int i = 0; i < F0; i++) {
        const float xi = xr[i];
        al += xi * sWl[i * H1 + j];
        ar += xi * sWr[i * H1 + j];
    }
    const int v = vbase + vloc;
    g_Y1[v * H1 + j] = al;
    g_S1[v * H1 + j] = ar + sB[j];
}

// ---------------- layer 1 scatter: A1[dst] += Y1[src]; cnt[dst]++ ----------------
__global__ void k_scatter1() {
    const int e = blockIdx.x * blockDim.x + threadIdx.x;
    if (e >= NE) return;
    const int s = g_src[e];
    const int d = g_dst[e];
    const float4* y = (const float4*)(g_Y1 + s * H1);   // 128B L2-resident row
    float* a = g_A1 + d * H1;
#pragma unroll
    for (int k = 0; k < 8; k++) red_add_v4(a + 4 * k, y[k]);
    atomicAdd(&g_cnt[d], 1);                            // return unused -> RED
}

// ---------------- finalize layer 1 + transform layer 2 ----------------
// h1 = relu(A1/max(cnt,1) + S1); Y2 = h1@W2l; S2 = h1@W2r + b2.
// 256 threads = 16 nodes; h1 staged in smem.
__global__ void k_layer2(const float* __restrict__ W2l,
                         const float* __restrict__ W2r,
                         const float* __restrict__ b2) {
    __shared__ float sWl[H1 * H2];
    __shared__ float sWr[H1 * H2];
    __shared__ float sB[H2];
    __shared__ float sH[16 * H1];
    const int tid = threadIdx.x;
    for (int i = tid; i < H1 * H2; i += 256) { sWl[i] = W2l[i]; sWr[i] = W2r[i]; }
    if (tid < H2) sB[tid] = b2[tid];
    const int vbase = blockIdx.x * 16;                   // 100000 % 16 == 0
    for (int idx = tid; idx < 16 * H1; idx += 256) {
        const int v  = vbase + (idx >> 5);
        const int gi = vbase * H1 + idx;                 // contiguous, coalesced
        const float c = (float)max(g_cnt[v], 1);
        sH[idx] = fmaxf(g_A1[gi] / c + g_S1[gi], 0.f);
    }
    __syncthreads();

    const int vloc = tid >> 4;
    const int k    = tid & 15;
    const float* hr = &sH[vloc * H1];
    float al = 0.f, ar = 0.f;
#pragma unroll
    for (int j = 0; j < H1; j++) {
        const float h = hr[j];
        al += h * sWl[j * H2 + k];
        ar += h * sWr[j * H2 + k];
    }
    const int v = vbase + vloc;
    g_Y2[v * H2 + k] = al;
    g_S2[v * H2 + k] = ar + sB[k];
}

// ---------------- layer 2 scatter: A2[dst] += Y2[src] ----------------
__global__ void k_scatter2() {
    const int e = blockIdx.x * blockDim.x + threadIdx.x;
    if (e >= NE) return;
    const int s = g_src[e];
    const int d = g_dst[e];
    const float4* y = (const float4*)(g_Y2 + s * H2);
    float* a = g_A2 + d * H2;
#pragma unroll
    for (int k = 0; k < 4; k++) red_add_v4(a + 4 * k, y[k]);
}

// ---------------- finalize layer 2 + output linear ----------------
__global__ void k_final(const float* __restrict__ Wlin,
                        const float* __restrict__ blin,
                        float* __restrict__ out) {
    const int v = blockIdx.x * blockDim.x + threadIdx.x;
    if (v >= NND) return;
    const float inv = 1.0f / (float)max(g_cnt[v], 1);
    float acc0 = blin[0], acc1 = blin[1];
    const float4* a4 = (const float4*)(g_A2 + v * H2);
    const float4* s4 = (const float4*)(g_S2 + v * H2);
#pragma unroll
    for (int q = 0; q < 4; q++) {
        const float4 a = a4[q];
        const float4 s = s4[q];
        float h;
        h = fmaxf(fmaf(a.x, inv, s.x), 0.f); acc0 += h * Wlin[(q*4+0)*2]; acc1 += h * Wlin[(q*4+0)*2+1];
        h = fmaxf(fmaf(a.y, inv, s.y), 0.f); acc0 += h * Wlin[(q*4+1)*2]; acc1 += h * Wlin[(q*4+1)*2+1];
        h = fmaxf(fmaf(a.z, inv, s.z), 0.f); acc0 += h * Wlin[(q*4+2)*2]; acc1 += h * Wlin[(q*4+2)*2+1];
        h = fmaxf(fmaf(a.w, inv, s.w), 0.f); acc0 += h * Wlin[(q*4+3)*2]; acc1 += h * Wlin[(q*4+3)*2+1];
    }
    out[v * 2 + 0] = acc0;
    out[v * 2 + 1] = acc1;
}

extern "C" void kernel_launch(void* const* d_in, const int* in_sizes, int n_in,
                              void* d_out, int out_size) {
    const float* x    = (const float*)d_in[0];
    const void*  ei   = d_in[1];
    const float* W1l  = (const float*)d_in[2];
    const float* W1r  = (const float*)d_in[3];
    const float* b1   = (const float*)d_in[4];
    const float* W2l  = (const float*)d_in[5];
    const float* W2r  = (const float*)d_in[6];
    const float* b2   = (const float*)d_in[7];
    const float* Wlin = (const float*)d_in[8];
    const float* blin = (const float*)d_in[9];
    float* out = (float*)d_out;

    k_detect<<<1, 256>>>((const unsigned int*)ei);
    k_convert_zero<<<2048, 256>>>(ei);
    k_transform1<<<NND / 8, 256>>>(x, W1l, W1r, b1);
    k_scatter1<<<(NE + 255) / 256, 256>>>();
    k_layer2<<<NND / 16, 256>>>(W2l, W2r, b2);
    k_scatter2<<<(NE + 255) / 256, 256>>>();
    k_final<<<(NND + 255) / 256, 256>>>(Wlin, blin, out);
}

// round 8
// speedup vs baseline: 1.3392x; 1.3392x over previous
#include <cuda_runtime.h>

#define NND 100000
#define NE  1600000
#define F0  48
#define H1  32
#define H2  16

#define SCAN_BLOCKS 98          // 98 * 1024 >= 100000

// ---------------- scratch (static device globals; allocation is forbidden) ----------------
__device__ int g_is64;
__device__ int g_cnt[NND];            // per-dst degree (histogram)
__device__ int g_fill[NND];           // per-dst fill cursor
__device__ int g_off[NND + 1];        // CSR row offsets
__device__ int g_bsum[SCAN_BLOCKS];
__device__ int g_bscan[SCAN_BLOCKS];
__device__ int g_csr[NE];             // CSR column (src) indices, grouped by dst
__device__ __align__(16) float g_Y1[NND * H1];   // x @ W1l
__device__ __align__(16) float g_S1[NND * H1];   // x @ W1r + b1
__device__ __align__(16) float g_H1[NND * H1];   // layer-1 activations
__device__ __align__(16) float g_Y2[NND * H2];   // h1 @ W2l
__device__ __align__(16) float g_S2[NND * H2];   // h1 @ W2r + b2

// ---------------- init: zero counters; block 0 detects edge_index dtype ----------------
// int64 (LE) edge_index has all-zero odd 32-bit words (node ids < 2^17).
__global__ void k_init(const unsigned int* __restrict__ p32) {
    const int t0 = blockIdx.x * blockDim.x + threadIdx.x;
    const int stride = gridDim.x * blockDim.x;
    for (int i = t0; i < NND; i += stride) { g_cnt[i] = 0; g_fill[i] = 0; }
    if (blockIdx.x == 0) {
        __shared__ int anynz;
        if (threadIdx.x == 0) anynz = 0;
        __syncthreads();
        if (p32[2 * threadIdx.x + 1] != 0) anynz = 1;   // benign same-value race
        __syncthreads();
        if (threadIdx.x == 0) g_is64 = (anynz == 0);
    }
}

// ---------------- histogram of dst degrees ----------------
__global__ void k_hist(const void* __restrict__ ei) {
    const int t0 = blockIdx.x * blockDim.x + threadIdx.x;
    const int stride = gridDim.x * blockDim.x;
    const int is64 = g_is64;
    if (is64) {
        const long long* p = (const long long*)ei;
        for (int e = t0; e < NE; e += stride) atomicAdd(&g_cnt[(int)p[NE + e]], 1);
    } else {
        const int* p = (const int*)ei;
        for (int e = t0; e < NE; e += stride) atomicAdd(&g_cnt[p[NE + e]], 1);
    }
}

// ---------------- exclusive scan of g_cnt into g_off (3 kernels) ----------------
__global__ void k_scanA() {          // 98 blocks x 256 threads, 4 elems/thread
    __shared__ int sd[256];
    const int tid = threadIdx.x;
    const int base = blockIdx.x * 1024 + tid * 4;
    int c[4];
#pragma unroll
    for (int q = 0; q < 4; q++) c[q] = (base + q < NND) ? g_cnt[base + q] : 0;
    const int tsum = c[0] + c[1] + c[2] + c[3];
    sd[tid] = tsum;
    __syncthreads();
    for (int off = 1; off < 256; off <<= 1) {
        const int v = (tid >= off) ? sd[tid - off] : 0;
        __syncthreads();
        sd[tid] += v;
        __syncthreads();
    }
    int o = sd[tid] - tsum;          // exclusive prefix within block
#pragma unroll
    for (int q = 0; q < 4; q++) { if (base + q < NND) g_off[base + q] = o; o += c[q]; }
    if (tid == 255) g_bsum[blockIdx.x] = sd[255];
}

__global__ void k_scanB() {          // 1 block, 128 threads over 98 block sums
    __shared__ int sd[128];
    const int tid = threadIdx.x;
    const int v = (tid < SCAN_BLOCKS) ? g_bsum[tid] : 0;
    sd[tid] = v;
    __syncthreads();
    for (int off = 1; off < 128; off <<= 1) {
        const int u = (tid >= off) ? sd[tid - off] : 0;
        __syncthreads();
        sd[tid] += u;
        __syncthreads();
    }
    if (tid < SCAN_BLOCKS) g_bscan[tid] = sd[tid] - v;   // exclusive
}

__global__ void k_scanC() {
    const int i = blockIdx.x * blockDim.x + threadIdx.x;
    if (i > NND) return;
    if (i == NND) g_off[NND] = NE;
    else          g_off[i] += g_bscan[i >> 10];
}

// ---------------- CSR fill: slot via int atomic cursor (spread addresses) ----------------
__global__ void k_fill(const void* __restrict__ ei) {
    const int e = blockIdx.x * blockDim.x + threadIdx.x;
    if (e >= NE) return;
    int s, d;
    if (g_is64) {
        const long long* p = (const long long*)ei;
        s = (int)p[e]; d = (int)p[NE + e];
    } else {
        const int* p = (const int*)ei;
        s = p[e]; d = p[NE + e];
    }
    const int pos = g_off[d] + atomicAdd(&g_fill[d], 1);
    g_csr[pos] = s;
}

// ---------------- layer 1 transforms: Y1 = x@W1l, S1 = x@W1r + b1 ----------------
__global__ void k_transform1(const float* __restrict__ x,
                             const float* __restrict__ Wl,
                             const float* __restrict__ Wr,
                             const float* __restrict__ b) {
    __shared__ float sWl[F0 * H1];
    __shared__ float sWr[F0 * H1];
    __shared__ float sB[H1];
    __shared__ float sX[8 * F0];
    const int tid = threadIdx.x;
    for (int i = tid; i < F0 * H1; i += 256) { sWl[i] = Wl[i]; sWr[i] = Wr[i]; }
    if (tid < H1) sB[tid] = b[tid];
    const int vbase = blockIdx.x * 8;                    // 100000 % 8 == 0
    for (int i = tid; i < 8 * F0; i += 256) sX[i] = x[vbase * F0 + i];
    __syncthreads();

    const int vloc = tid >> 5;
    const int j    = tid & 31;
    const float* xr = &sX[vloc * F0];
    float al = 0.f, ar = 0.f;
#pragma unroll
    for (int i = 0; i < F0; i++) {
        const float xi = xr[i];
        al += xi * sWl[i * H1 + j];
        ar += xi * sWr[i * H1 + j];
    }
    const int v = vbase + vloc;
    g_Y1[v * H1 + j] = al;
    g_S1[v * H1 + j] = ar + sB[j];
}

// ---------------- layer 1 gather + finalize: h1 = relu(mean(Y1[nbrs]) + S1) ----------------
// Warp per node, column per lane. Neighbor ids loaded 32-at-a-time, shfl-broadcast.
__global__ void k_gather1() {
    const int warp = (blockIdx.x * blockDim.x + threadIdx.x) >> 5;
    if (warp >= NND) return;
    const int lane = threadIdx.x & 31;
    const int start = g_off[warp];
    const int end   = g_off[warp + 1];
    float acc = 0.f;
    for (int p = start; p < end; p += 32) {
        const int n = min(32, end - p);
        const int idx = (lane < n) ? g_csr[p + lane] : 0;
        for (int j = 0; j < n; j++) {
            const int s = __shfl_sync(0xffffffffu, idx, j);
            acc += g_Y1[s * H1 + lane];                  // coalesced 128B row, L2-hit
        }
    }
    const float inv = 1.0f / (float)max(end - start, 1);
    g_H1[warp * H1 + lane] = fmaxf(fmaf(acc, inv, g_S1[warp * H1 + lane]), 0.f);
}

// ---------------- layer 2 transforms: Y2 = h1@W2l, S2 = h1@W2r + b2 ----------------
__global__ void k_layer2(const float* __restrict__ W2l,
                         const float* __restrict__ W2r,
                         const float* __restrict__ b2) {
    __shared__ float sWl[H1 * H2];
    __shared__ float sWr[H1 * H2];
    __shared__ float sB[H2];
    __shared__ float sH[16 * H1];
    const int tid = threadIdx.x;
    for (int i = tid; i < H1 * H2; i += 256) { sWl[i] = W2l[i]; sWr[i] = W2r[i]; }
    if (tid < H2) sB[tid] = b2[tid];
    const int vbase = blockIdx.x * 16;                   // 100000 % 16 == 0
    for (int idx = tid; idx < 16 * H1; idx += 256) sH[idx] = g_H1[vbase * H1 + idx];
    __syncthreads();

    const int vloc = tid >> 4;
    const int k    = tid & 15;
    const float* hr = &sH[vloc * H1];
    float al = 0.f, ar = 0.f;
#pragma unroll
    for (int j = 0; j < H1; j++) {
        const float h = hr[j];
        al += h * sWl[j * H2 + k];
        ar += h * sWr[j * H2 + k];
    }
    const int v = vbase + vloc;
    g_Y2[v * H2 + k] = al;
    g_S2[v * H2 + k] = ar + sB[k];
}

// ---------------- layer 2 gather + finalize + output linear (fused) ----------------
// 16 threads per node (2 nodes per warp). 16-wide shuffles stay within one group,
// so divergent loop trip counts between the two half-warps are safe.
__global__ void k_gather2(const float* __restrict__ Wlin,
                          const float* __restrict__ blin,
                          float* __restrict__ out) {
    const int gthread = blockIdx.x * blockDim.x + threadIdx.x;
    const int v = gthread >> 4;
    if (v >= NND) return;
    const int k = threadIdx.x & 15;
    const unsigned gmask = 0xFFFFu << (threadIdx.x & 16);

    const int start = g_off[v];
    const int end   = g_off[v + 1];
    float acc = 0.f;
    for (int p = start; p < end; p += 16) {
        const int n = min(16, end - p);
        const int idx = (k < n) ? g_csr[p + k] : 0;
        for (int j = 0; j < n; j++) {
            const int s = __shfl_sync(gmask, idx, j, 16);
            acc += g_Y2[s * H2 + k];                     // coalesced 64B row, L2-hit
        }
    }
    const float inv = 1.0f / (float)max(end - start, 1);
    const float h = fmaxf(fmaf(acc, inv, g_S2[v * H2 + k]), 0.f);

    float p0 = h * Wlin[k * 2 + 0];
    float p1 = h * Wlin[k * 2 + 1];
#pragma unroll
    for (int off = 8; off >= 1; off >>= 1) {
        p0 += __shfl_down_sync(gmask, p0, off, 16);
        p1 += __shfl_down_sync(gmask, p1, off, 16);
    }
    if (k == 0) {
        out[v * 2 + 0] = p0 + blin[0];
        out[v * 2 + 1] = p1 + blin[1];
    }
}

extern "C" void kernel_launch(void* const* d_in, const int* in_sizes, int n_in,
                              void* d_out, int out_size) {
    const float* x    = (const float*)d_in[0];
    const void*  ei   = d_in[1];
    const float* W1l  = (const float*)d_in[2];
    const float* W1r  = (const float*)d_in[3];
    const float* b1   = (const float*)d_in[4];
    const float* W2l  = (const float*)d_in[5];
    const float* W2r  = (const float*)d_in[6];
    const float* b2   = (const float*)d_in[7];
    const float* Wlin = (const float*)d_in[8];
    const float* blin = (const float*)d_in[9];
    float* out = (float*)d_out;

    k_init<<<392, 256>>>((const unsigned int*)ei);
    k_hist<<<1024, 256>>>(ei);
    k_scanA<<<SCAN_BLOCKS, 256>>>();
    k_scanB<<<1, 128>>>();
    k_scanC<<<(NND + 256) / 256, 256>>>();
    k_fill<<<(NE + 255) / 256, 256>>>(ei);
    k_transform1<<<NND / 8, 256>>>(x, W1l, W1r, b1);
    k_gather1<<<(NND * 32 + 255) / 256, 256>>>();
    k_layer2<<<NND / 16, 256>>>(W2l, W2r, b2);
    k_gather2<<<(NND * 16 + 255) / 256, 256>>>(Wlin, blin, out);
}